// round 10
// baseline (speedup 1.0000x reference)
#include <cuda_runtime.h>
#include <cuda_bf16.h>
#include <math.h>

#define D 128
#define MAXN 50176   // capacity for node scratch (N=50000)
#define MAXE 600064  // capacity for edge scratch (E=600000)

// Scratch (allocation-free rule: __device__ globals)
__device__ float g_agg [(size_t)MAXN * D];
__device__ float g_h1  [(size_t)MAXN * D];
__device__ float g_h2  [(size_t)MAXN * D];
__device__ int   g_cnt [MAXN];
__device__ int   g_offs[MAXN];
__device__ int   g_cur [MAXN];
__device__ int   g_ebuf[MAXE];

// ---------------------------------------------------------------------------
// CSR build: count -> scan -> fill
// ---------------------------------------------------------------------------
__global__ void zero_int_kernel(int* p, int n) {
    int i = blockIdx.x * blockDim.x + threadIdx.x;
    if (i < n) p[i] = 0;
}

__global__ void count_kernel(const int* __restrict__ ei, int E, int N,
                             int* __restrict__ cnt) {
    int e = blockIdx.x * blockDim.x + threadIdx.x;
    if (e < E) {
        int d = ei[E + e];  // dst row
        if ((unsigned)d < (unsigned)N) atomicAdd(&cnt[d], 1);
    }
}

// single-block exclusive scan over cnt -> offs (and a working copy cur)
__global__ void scan_kernel(const int* __restrict__ cnt, int N,
                            int* __restrict__ offs, int* __restrict__ cur) {
    __shared__ int wsum[32];
    __shared__ int sbase;
    int tid = threadIdx.x, lane = tid & 31, w = tid >> 5;
    if (tid == 0) sbase = 0;
    __syncthreads();
    for (int start = 0; start < N; start += 1024) {
        int i = start + tid;
        int v = (i < N) ? cnt[i] : 0;
        int s = v;  // inclusive warp scan
#pragma unroll
        for (int o = 1; o < 32; o <<= 1) {
            int t = __shfl_up_sync(0xffffffffu, s, o);
            if (lane >= o) s += t;
        }
        if (lane == 31) wsum[w] = s;
        __syncthreads();
        if (w == 0) {
            int ws = wsum[lane];
#pragma unroll
            for (int o = 1; o < 32; o <<= 1) {
                int t = __shfl_up_sync(0xffffffffu, ws, o);
                if (lane >= o) ws += t;
            }
            wsum[lane] = ws;  // inclusive over warps
        }
        __syncthreads();
        int wbase = (w > 0) ? wsum[w - 1] : 0;
        int excl = sbase + wbase + s - v;
        if (i < N) { offs[i] = excl; cur[i] = excl; }
        __syncthreads();
        if (tid == 0) sbase += wsum[31];
        __syncthreads();
    }
}

__global__ void fill_kernel(const int* __restrict__ ei, int E, int N,
                            int* __restrict__ cur, int* __restrict__ ebuf) {
    int e = blockIdx.x * blockDim.x + threadIdx.x;
    if (e < E) {
        int s = ei[e];
        int d = ei[E + e];
        if ((unsigned)d < (unsigned)N && (unsigned)s < (unsigned)N) {
            int p = atomicAdd(&cur[d], 1);
            ebuf[p] = s;
        }
    }
}

// ---------------------------------------------------------------------------
// Warp-per-node CSR gather with mean folded in (no atomics, no zero pass).
// lane j accumulates columns j, j+32, j+64, j+96.
// ---------------------------------------------------------------------------
__global__ void gather_kernel(const float* __restrict__ x,
                              const int* __restrict__ ebuf,
                              const int* __restrict__ offs,
                              const int* __restrict__ cnt,
                              int N, float* __restrict__ agg) {
    int node = (blockIdx.x * blockDim.x + threadIdx.x) >> 5;
    int lane = threadIdx.x & 31;
    if (node >= N) return;
    int deg  = cnt[node];
    int base = offs[node];
    float a0 = 0.f, a1 = 0.f, a2 = 0.f, a3 = 0.f;
    int i = 0;
    for (; i + 2 <= deg; i += 2) {
        int s0 = __ldg(ebuf + base + i);
        int s1 = __ldg(ebuf + base + i + 1);
        const float* r0 = x + (size_t)s0 * D;
        const float* r1 = x + (size_t)s1 * D;
        float v00 = __ldg(r0 + lane),      v10 = __ldg(r1 + lane);
        float v01 = __ldg(r0 + lane + 32), v11 = __ldg(r1 + lane + 32);
        float v02 = __ldg(r0 + lane + 64), v12 = __ldg(r1 + lane + 64);
        float v03 = __ldg(r0 + lane + 96), v13 = __ldg(r1 + lane + 96);
        a0 += v00 + v10; a1 += v01 + v11; a2 += v02 + v12; a3 += v03 + v13;
    }
    if (i < deg) {
        int s0 = __ldg(ebuf + base + i);
        const float* r0 = x + (size_t)s0 * D;
        a0 += __ldg(r0 + lane);      a1 += __ldg(r0 + lane + 32);
        a2 += __ldg(r0 + lane + 64); a3 += __ldg(r0 + lane + 96);
    }
    float iv = 1.0f / (float)max(deg, 1);
    float* ar = agg + (size_t)node * D;
    ar[lane]      = a0 * iv;
    ar[lane + 32] = a1 * iv;
    ar[lane + 64] = a2 * iv;
    ar[lane + 96] = a3 * iv;
}

// ---------------------------------------------------------------------------
// Fused conv GEMM with packed f32x2 FMA (FFMA2):
//   out = epilogue( (HAS_AGG ? A @ Wl : 0) + bias + X @ Wr )
//   A is the already-mean-aggregated matrix.
// 128x128 tile per CTA, 256 threads, 8 rows x 8 cols per thread.
// Rows: ty + 16*i. Cols: 2*tx + 32*j (+0/+1 within the f32x2 pair) —
// LDS.64 B-loads hit all 32 banks exactly once across the 16 tx values.
// ---------------------------------------------------------------------------
#define SMEM_FLOATS (128 * 132)
#define SMEM_BYTES  (SMEM_FLOATS * 4)   // 67584 B

template <bool HAS_AGG, bool NORM_RELU>
__global__ void __launch_bounds__(256, 2)
conv_kernel(const float* __restrict__ A, const float* __restrict__ X,
            const float* __restrict__ Wl, const float* __restrict__ bias,
            const float* __restrict__ Wr, float* __restrict__ out, int N)
{
    extern __shared__ float sm[];
    float* As = sm;               // [128][36] padded row stride
    float* Ws = sm + 128 * 36;    // [32][128]

    const int tid = threadIdx.x;
    const int tx = tid & 15;      // column group: cols 2*tx + 32*j (+1)
    const int ty = tid >> 4;      // row group: rows ty + 16*i
    const int row0 = blockIdx.x * 128;

    unsigned long long acc2[8][4];
#pragma unroll
    for (int i = 0; i < 8; ++i)
#pragma unroll
        for (int j = 0; j < 4; ++j) acc2[i][j] = 0ull;

    for (int pass = HAS_AGG ? 0 : 1; pass < 2; ++pass) {
        const float* __restrict__ Aptr = (pass == 0) ? A : X;
        const float* __restrict__ Wptr = (pass == 0) ? Wl : Wr;

        for (int k0 = 0; k0 < D; k0 += 32) {
            __syncthreads();
            // ---- stage A tile: 128 rows x 32 cols ----
            {
                int r = tid >> 1;
                int cbase = (tid & 1) * 16;
                int grow = row0 + r;
#pragma unroll
                for (int f = 0; f < 4; ++f) {
                    float4 v;
                    if (grow < N)
                        v = *(const float4*)(Aptr + (size_t)grow * D + k0 + cbase + f * 4);
                    else
                        v = make_float4(0.f, 0.f, 0.f, 0.f);
                    *(float4*)(As + r * 36 + cbase + f * 4) = v;
                }
            }
            // ---- stage W tile: 32 rows x 128 cols ----
            {
                int r = tid >> 3;
                int cbase = (tid & 7) * 16;
#pragma unroll
                for (int f = 0; f < 4; ++f) {
                    *(float4*)(Ws + r * 128 + cbase + f * 4) =
                        *(const float4*)(Wptr + (size_t)(k0 + r) * D + cbase + f * 4);
                }
            }
            __syncthreads();
            // ---- compute: 32 FFMA2 per k per thread ----
#pragma unroll
            for (int k = 0; k < 32; ++k) {
                unsigned long long b2[4];
#pragma unroll
                for (int j = 0; j < 4; ++j)
                    b2[j] = *(const unsigned long long*)(Ws + k * 128 + 2 * tx + 32 * j);
                unsigned long long a2[8];
#pragma unroll
                for (int i = 0; i < 8; ++i) {
                    unsigned int au = __float_as_uint(As[(ty + 16 * i) * 36 + k]);
                    asm("mov.b64 %0, {%1, %1};" : "=l"(a2[i]) : "r"(au));
                }
#pragma unroll
                for (int i = 0; i < 8; ++i)
#pragma unroll
                    for (int j = 0; j < 4; ++j)
                        asm("fma.rn.f32x2 %0, %1, %2, %0;"
                            : "+l"(acc2[i][j]) : "l"(a2[i]), "l"(b2[j]));
            }
        }
    }

    // ---- epilogue: smem round-trip for row-contiguous access ----
    __syncthreads();
    float* ep = sm;  // [128][132]
#pragma unroll
    for (int i = 0; i < 8; ++i)
#pragma unroll
        for (int j = 0; j < 4; ++j) {
            unsigned int lo, hi;
            asm("mov.b64 {%0, %1}, %2;" : "=r"(lo), "=r"(hi) : "l"(acc2[i][j]));
            float2 v2 = make_float2(__uint_as_float(lo), __uint_as_float(hi));
            *(float2*)(ep + (ty + 16 * i) * 132 + 2 * tx + 32 * j) = v2;
        }
    __syncthreads();

    const int wid = tid >> 5, lane = tid & 31;
#pragma unroll 1
    for (int rr = 0; rr < 16; ++rr) {
        int r = wid * 16 + rr;          // warp-uniform
        int grow = row0 + r;
        if (grow >= N) continue;        // warp-uniform guard
        float4 v  = *(const float4*)(ep + r * 132 + lane * 4);
        float4 bb = *(const float4*)(bias + lane * 4);
        v.x += bb.x; v.y += bb.y; v.z += bb.z; v.w += bb.w;
        if (NORM_RELU) {
            float ss = v.x * v.x + v.y * v.y + v.z * v.z + v.w * v.w;
#pragma unroll
            for (int o = 16; o > 0; o >>= 1) ss += __shfl_xor_sync(0xffffffffu, ss, o);
            float scale = 1.0f / fmaxf(sqrtf(ss), 1e-12f);
            v.x = fmaxf(v.x * scale, 0.0f);
            v.y = fmaxf(v.y * scale, 0.0f);
            v.z = fmaxf(v.z * scale, 0.0f);
            v.w = fmaxf(v.w * scale, 0.0f);
        }
        *(float4*)(out + (size_t)grow * D + lane * 4) = v;
    }
}

// ---------------------------------------------------------------------------
extern "C" void kernel_launch(void* const* d_in, const int* in_sizes, int n_in,
                              void* d_out, int out_size)
{
    const float* x   = (const float*)d_in[0];
    const int*   ei  = (const int*)d_in[1];     // int32 (JAX x64 disabled)
    const float* W1l = (const float*)d_in[2];
    const float* b1  = (const float*)d_in[3];
    const float* W1r = (const float*)d_in[4];
    const float* W2l = (const float*)d_in[5];
    const float* b2  = (const float*)d_in[6];
    const float* W2r = (const float*)d_in[7];
    const float* Wf  = (const float*)d_in[8];
    const float* bf  = (const float*)d_in[9];
    float*       out = (float*)d_out;

    const int N = in_sizes[0] / D;
    const int E = in_sizes[1] / 2;

    float *agg, *h1, *h2;
    int *cnt, *offs, *cur, *ebuf;
    cudaGetSymbolAddress((void**)&agg,  g_agg);
    cudaGetSymbolAddress((void**)&h1,   g_h1);
    cudaGetSymbolAddress((void**)&h2,   g_h2);
    cudaGetSymbolAddress((void**)&cnt,  g_cnt);
    cudaGetSymbolAddress((void**)&offs, g_offs);
    cudaGetSymbolAddress((void**)&cur,  g_cur);
    cudaGetSymbolAddress((void**)&ebuf, g_ebuf);

    cudaFuncSetAttribute(conv_kernel<true,  true >, cudaFuncAttributeMaxDynamicSharedMemorySize, SMEM_BYTES);
    cudaFuncSetAttribute(conv_kernel<false, false>, cudaFuncAttributeMaxDynamicSharedMemorySize, SMEM_BYTES);

    const int convGrid = (N + 127) / 128;
    const int gathGrid = (N * 32 + 255) / 256;
    const int edgeGrid = (E + 255) / 256;
    const int nodeGrid = (N + 255) / 256;

    // ---- CSR build (once; reused by both layers) ----
    zero_int_kernel<<<nodeGrid, 256>>>(cnt, N);
    count_kernel<<<edgeGrid, 256>>>(ei, E, N, cnt);
    scan_kernel<<<1, 1024>>>(cnt, N, offs, cur);
    fill_kernel<<<edgeGrid, 256>>>(ei, E, N, cur, ebuf);

    // ---- layer 1 ----
    gather_kernel<<<gathGrid, 256>>>(x, ebuf, offs, cnt, N, agg);
    conv_kernel<true, true><<<convGrid, 256, SMEM_BYTES>>>(agg, x, W1l, b1, W1r, h1, N);

    // ---- layer 2 ----
    gather_kernel<<<gathGrid, 256>>>(h1, ebuf, offs, cnt, N, agg);
    conv_kernel<true, true><<<convGrid, 256, SMEM_BYTES>>>(agg, h1, W2l, b2, W2r, h2, N);

    // ---- final fc ----
    conv_kernel<false, false><<<convGrid, 256, SMEM_BYTES>>>(nullptr, h2, nullptr, bf, Wf, out, N);
}

// round 12
// speedup vs baseline: 1.0050x; 1.0050x over previous
#include <cuda_runtime.h>
#include <cuda_bf16.h>
#include <math.h>

#define D 128
#define MAXN 50176   // capacity for node scratch (N=50000)
#define MAXE 600064  // capacity for edge scratch (E=600000)

// Scratch (allocation-free rule: __device__ globals)
__device__ float g_agg [(size_t)MAXN * D];
__device__ float g_h1  [(size_t)MAXN * D];
__device__ float g_h2  [(size_t)MAXN * D];
__device__ int   g_cnt [MAXN];
__device__ int   g_offs[MAXN];
__device__ int   g_cur [MAXN];
__device__ int   g_ebuf[MAXE];

// ---------------------------------------------------------------------------
// CSR build: count -> scan -> fill
// ---------------------------------------------------------------------------
__global__ void zero_int_kernel(int* p, int n) {
    int i = blockIdx.x * blockDim.x + threadIdx.x;
    if (i < n) p[i] = 0;
}

__global__ void count_kernel(const int* __restrict__ ei, int E, int N,
                             int* __restrict__ cnt) {
    int e = blockIdx.x * blockDim.x + threadIdx.x;
    if (e < E) {
        int d = ei[E + e];  // dst row
        if ((unsigned)d < (unsigned)N) atomicAdd(&cnt[d], 1);
    }
}

// single-block exclusive scan over cnt -> offs (and a working copy cur)
__global__ void scan_kernel(const int* __restrict__ cnt, int N,
                            int* __restrict__ offs, int* __restrict__ cur) {
    __shared__ int wsum[32];
    __shared__ int sbase;
    int tid = threadIdx.x, lane = tid & 31, w = tid >> 5;
    if (tid == 0) sbase = 0;
    __syncthreads();
    for (int start = 0; start < N; start += 1024) {
        int i = start + tid;
        int v = (i < N) ? cnt[i] : 0;
        int s = v;  // inclusive warp scan
#pragma unroll
        for (int o = 1; o < 32; o <<= 1) {
            int t = __shfl_up_sync(0xffffffffu, s, o);
            if (lane >= o) s += t;
        }
        if (lane == 31) wsum[w] = s;
        __syncthreads();
        if (w == 0) {
            int ws = wsum[lane];
#pragma unroll
            for (int o = 1; o < 32; o <<= 1) {
                int t = __shfl_up_sync(0xffffffffu, ws, o);
                if (lane >= o) ws += t;
            }
            wsum[lane] = ws;  // inclusive over warps
        }
        __syncthreads();
        int wbase = (w > 0) ? wsum[w - 1] : 0;
        int excl = sbase + wbase + s - v;
        if (i < N) { offs[i] = excl; cur[i] = excl; }
        __syncthreads();
        if (tid == 0) sbase += wsum[31];
        __syncthreads();
    }
}

__global__ void fill_kernel(const int* __restrict__ ei, int E, int N,
                            int* __restrict__ cur, int* __restrict__ ebuf) {
    int e = blockIdx.x * blockDim.x + threadIdx.x;
    if (e < E) {
        int s = ei[e];
        int d = ei[E + e];
        if ((unsigned)d < (unsigned)N && (unsigned)s < (unsigned)N) {
            int p = atomicAdd(&cur[d], 1);
            ebuf[p] = s;
        }
    }
}

// ---------------------------------------------------------------------------
// Warp-per-node CSR gather with mean folded in (no atomics, no zero pass).
// lane j accumulates columns j, j+32, j+64, j+96.
// ---------------------------------------------------------------------------
__global__ void gather_kernel(const float* __restrict__ x,
                              const int* __restrict__ ebuf,
                              const int* __restrict__ offs,
                              const int* __restrict__ cnt,
                              int N, float* __restrict__ agg) {
    int node = (blockIdx.x * blockDim.x + threadIdx.x) >> 5;
    int lane = threadIdx.x & 31;
    if (node >= N) return;
    int deg  = cnt[node];
    int base = offs[node];
    float a0 = 0.f, a1 = 0.f, a2 = 0.f, a3 = 0.f;
    int i = 0;
    for (; i + 2 <= deg; i += 2) {
        int s0 = __ldg(ebuf + base + i);
        int s1 = __ldg(ebuf + base + i + 1);
        const float* r0 = x + (size_t)s0 * D;
        const float* r1 = x + (size_t)s1 * D;
        float v00 = __ldg(r0 + lane),      v10 = __ldg(r1 + lane);
        float v01 = __ldg(r0 + lane + 32), v11 = __ldg(r1 + lane + 32);
        float v02 = __ldg(r0 + lane + 64), v12 = __ldg(r1 + lane + 64);
        float v03 = __ldg(r0 + lane + 96), v13 = __ldg(r1 + lane + 96);
        a0 += v00 + v10; a1 += v01 + v11; a2 += v02 + v12; a3 += v03 + v13;
    }
    if (i < deg) {
        int s0 = __ldg(ebuf + base + i);
        const float* r0 = x + (size_t)s0 * D;
        a0 += __ldg(r0 + lane);      a1 += __ldg(r0 + lane + 32);
        a2 += __ldg(r0 + lane + 64); a3 += __ldg(r0 + lane + 96);
    }
    float iv = 1.0f / (float)max(deg, 1);
    float* ar = agg + (size_t)node * D;
    ar[lane]      = a0 * iv;
    ar[lane + 32] = a1 * iv;
    ar[lane + 64] = a2 * iv;
    ar[lane + 96] = a3 * iv;
}

// ---------------------------------------------------------------------------
// Fused conv GEMM with packed f32x2 FMA (FFMA2):
//   out = epilogue( (HAS_AGG ? A @ Wl : 0) + bias + X @ Wr )
//   A is the already-mean-aggregated matrix.
// 128x128 tile per CTA, 256 threads, 8 rows x 8 cols per thread.
// Rows: ty + 16*i. Cols: 2*tx + 32*j (+0/+1 within the f32x2 pair) —
// LDS.64 B-loads hit all 32 banks exactly once across the 16 tx values.
// ---------------------------------------------------------------------------
#define SMEM_FLOATS (128 * 132)
#define SMEM_BYTES  (SMEM_FLOATS * 4)   // 67584 B

template <bool HAS_AGG, bool NORM_RELU>
__global__ void __launch_bounds__(256, 2)
conv_kernel(const float* __restrict__ A, const float* __restrict__ X,
            const float* __restrict__ Wl, const float* __restrict__ bias,
            const float* __restrict__ Wr, float* __restrict__ out, int N)
{
    extern __shared__ float sm[];
    float* As = sm;               // [128][36] padded row stride
    float* Ws = sm + 128 * 36;    // [32][128]

    const int tid = threadIdx.x;
    const int tx = tid & 15;      // column group: cols 2*tx + 32*j (+1)
    const int ty = tid >> 4;      // row group: rows ty + 16*i
    const int row0 = blockIdx.x * 128;

    unsigned long long acc2[8][4];
#pragma unroll
    for (int i = 0; i < 8; ++i)
#pragma unroll
        for (int j = 0; j < 4; ++j) acc2[i][j] = 0ull;

    for (int pass = HAS_AGG ? 0 : 1; pass < 2; ++pass) {
        const float* __restrict__ Aptr = (pass == 0) ? A : X;
        const float* __restrict__ Wptr = (pass == 0) ? Wl : Wr;

        for (int k0 = 0; k0 < D; k0 += 32) {
            __syncthreads();
            // ---- stage A tile: 128 rows x 32 cols ----
            {
                int r = tid >> 1;
                int cbase = (tid & 1) * 16;
                int grow = row0 + r;
#pragma unroll
                for (int f = 0; f < 4; ++f) {
                    float4 v;
                    if (grow < N)
                        v = *(const float4*)(Aptr + (size_t)grow * D + k0 + cbase + f * 4);
                    else
                        v = make_float4(0.f, 0.f, 0.f, 0.f);
                    *(float4*)(As + r * 36 + cbase + f * 4) = v;
                }
            }
            // ---- stage W tile: 32 rows x 128 cols ----
            {
                int r = tid >> 3;
                int cbase = (tid & 7) * 16;
#pragma unroll
                for (int f = 0; f < 4; ++f) {
                    *(float4*)(Ws + r * 128 + cbase + f * 4) =
                        *(const float4*)(Wptr + (size_t)(k0 + r) * D + cbase + f * 4);
                }
            }
            __syncthreads();
            // ---- compute: 32 FFMA2 per k per thread ----
#pragma unroll
            for (int k = 0; k < 32; ++k) {
                unsigned long long b2[4];
#pragma unroll
                for (int j = 0; j < 4; ++j)
                    b2[j] = *(const unsigned long long*)(Ws + k * 128 + 2 * tx + 32 * j);
                unsigned long long a2[8];
#pragma unroll
                for (int i = 0; i < 8; ++i) {
                    unsigned int au = __float_as_uint(As[(ty + 16 * i) * 36 + k]);
                    asm("mov.b64 %0, {%1, %1};" : "=l"(a2[i]) : "r"(au));
                }
#pragma unroll
                for (int i = 0; i < 8; ++i)
#pragma unroll
                    for (int j = 0; j < 4; ++j)
                        asm("fma.rn.f32x2 %0, %1, %2, %0;"
                            : "+l"(acc2[i][j]) : "l"(a2[i]), "l"(b2[j]));
            }
        }
    }

    // ---- epilogue: smem round-trip for row-contiguous access ----
    __syncthreads();
    float* ep = sm;  // [128][132]
#pragma unroll
    for (int i = 0; i < 8; ++i)
#pragma unroll
        for (int j = 0; j < 4; ++j) {
            unsigned int lo, hi;
            asm("mov.b64 {%0, %1}, %2;" : "=r"(lo), "=r"(hi) : "l"(acc2[i][j]));
            float2 v2 = make_float2(__uint_as_float(lo), __uint_as_float(hi));
            *(float2*)(ep + (ty + 16 * i) * 132 + 2 * tx + 32 * j) = v2;
        }
    __syncthreads();

    const int wid = tid >> 5, lane = tid & 31;
#pragma unroll 1
    for (int rr = 0; rr < 16; ++rr) {
        int r = wid * 16 + rr;          // warp-uniform
        int grow = row0 + r;
        if (grow >= N) continue;        // warp-uniform guard
        float4 v  = *(const float4*)(ep + r * 132 + lane * 4);
        float4 bb = *(const float4*)(bias + lane * 4);
        v.x += bb.x; v.y += bb.y; v.z += bb.z; v.w += bb.w;
        if (NORM_RELU) {
            float ss = v.x * v.x + v.y * v.y + v.z * v.z + v.w * v.w;
#pragma unroll
            for (int o = 16; o > 0; o >>= 1) ss += __shfl_xor_sync(0xffffffffu, ss, o);
            float scale = 1.0f / fmaxf(sqrtf(ss), 1e-12f);
            v.x = fmaxf(v.x * scale, 0.0f);
            v.y = fmaxf(v.y * scale, 0.0f);
            v.z = fmaxf(v.z * scale, 0.0f);
            v.w = fmaxf(v.w * scale, 0.0f);
        }
        *(float4*)(out + (size_t)grow * D + lane * 4) = v;
    }
}

// ---------------------------------------------------------------------------
extern "C" void kernel_launch(void* const* d_in, const int* in_sizes, int n_in,
                              void* d_out, int out_size)
{
    const float* x   = (const float*)d_in[0];
    const int*   ei  = (const int*)d_in[1];     // int32 (JAX x64 disabled)
    const float* W1l = (const float*)d_in[2];
    const float* b1  = (const float*)d_in[3];
    const float* W1r = (const float*)d_in[4];
    const float* W2l = (const float*)d_in[5];
    const float* b2  = (const float*)d_in[6];
    const float* W2r = (const float*)d_in[7];
    const float* Wf  = (const float*)d_in[8];
    const float* bf  = (const float*)d_in[9];
    float*       out = (float*)d_out;

    const int N = in_sizes[0] / D;
    const int E = in_sizes[1] / 2;

    float *agg, *h1, *h2;
    int *cnt, *offs, *cur, *ebuf;
    cudaGetSymbolAddress((void**)&agg,  g_agg);
    cudaGetSymbolAddress((void**)&h1,   g_h1);
    cudaGetSymbolAddress((void**)&h2,   g_h2);
    cudaGetSymbolAddress((void**)&cnt,  g_cnt);
    cudaGetSymbolAddress((void**)&offs, g_offs);
    cudaGetSymbolAddress((void**)&cur,  g_cur);
    cudaGetSymbolAddress((void**)&ebuf, g_ebuf);

    cudaFuncSetAttribute(conv_kernel<true,  true >, cudaFuncAttributeMaxDynamicSharedMemorySize, SMEM_BYTES);
    cudaFuncSetAttribute(conv_kernel<false, false>, cudaFuncAttributeMaxDynamicSharedMemorySize, SMEM_BYTES);

    const int convGrid = (N + 127) / 128;
    const int gathGrid = (N * 32 + 255) / 256;
    const int edgeGrid = (E + 255) / 256;
    const int nodeGrid = (N + 255) / 256;

    // ---- CSR build (once; reused by both layers) ----
    zero_int_kernel<<<nodeGrid, 256>>>(cnt, N);
    count_kernel<<<edgeGrid, 256>>>(ei, E, N, cnt);
    scan_kernel<<<1, 1024>>>(cnt, N, offs, cur);
    fill_kernel<<<edgeGrid, 256>>>(ei, E, N, cur, ebuf);

    // ---- layer 1 ----
    gather_kernel<<<gathGrid, 256>>>(x, ebuf, offs, cnt, N, agg);
    conv_kernel<true, true><<<convGrid, 256, SMEM_BYTES>>>(agg, x, W1l, b1, W1r, h1, N);

    // ---- layer 2 ----
    gather_kernel<<<gathGrid, 256>>>(h1, ebuf, offs, cnt, N, agg);
    conv_kernel<true, true><<<convGrid, 256, SMEM_BYTES>>>(agg, h1, W2l, b2, W2r, h2, N);

    // ---- final fc ----
    conv_kernel<false, false><<<convGrid, 256, SMEM_BYTES>>>(nullptr, h2, nullptr, bf, Wf, out, N);
}